// round 1
// baseline (speedup 1.0000x reference)
#include <cuda_runtime.h>

// ---------------------------------------------------------------------------
// EfficientViT attention block, fp32 baseline.
//   K1: QKV = BN(W_{q,k,v} @ x)        (fused 768-row GEMM, BN epilogue)
//   K2: O   = softmax(Q K^T) V          (flash-attention, online softmax)
//   K3: out = BN(W_p @ relu(O))         (GEMM, relu on load, BN epilogue)
// ---------------------------------------------------------------------------

namespace {
constexpr int BATCH = 2;
constexpr int CIN   = 384;
constexpr int NPIX  = 3136;     // 56*56
constexpr int HEADS = 8;
constexpr int KD    = 16;
constexpr int DV    = 64;
constexpr int DH    = 512;
constexpr int OCOUT = 384;
constexpr int BH    = BATCH * HEADS;
constexpr int NT    = NPIX / 64;   // 49 tiles of 64 pixels
constexpr float EPSBN = 1e-5f;
}

// scratch (static device arrays: allocation-free per harness rules)
__device__ __align__(16) float g_Q[BH * NPIX * KD];   // (bh, n, kd)
__device__ __align__(16) float g_K[BH * NPIX * KD];   // (bh, n, kd)
__device__ __align__(16) float g_V[BH * NPIX * DV];   // (bh, n, d)
__device__ __align__(16) float g_O[BH * NPIX * DV];   // (bh, n, d)

// ---------------------------------------------------------------------------
// Kernel 1: fused QKV projection + folded BatchNorm.
// grid (49, 12, 2), block 256. Each block: 64 out-channels x 64 pixels.
// ---------------------------------------------------------------------------
__global__ __launch_bounds__(256, 3) void qkv_kernel(
    const float* __restrict__ x,
    const float* __restrict__ wq, const float* __restrict__ wk, const float* __restrict__ wv,
    const float* __restrict__ qg, const float* __restrict__ qb, const float* __restrict__ qm, const float* __restrict__ qv,
    const float* __restrict__ kg, const float* __restrict__ kb, const float* __restrict__ km, const float* __restrict__ kvv,
    const float* __restrict__ vg, const float* __restrict__ vb, const float* __restrict__ vm, const float* __restrict__ vvv)
{
    __shared__ __align__(16) float Ws[64][17];
    __shared__ __align__(16) float Xs[16][64];

    const int b   = blockIdx.z;
    const int oc0 = blockIdx.y * 64;
    const int n0  = blockIdx.x * 64;
    const int tid = threadIdx.x;
    const int tx  = tid & 15, ty = tid >> 4;

    const int wrow = tid >> 2, wseg = tid & 3;        // W tile loader: 64 rows x 4 segs
    const int xc   = tid >> 4, xn = (tid & 15) * 4;   // X tile loader: 16 ch x 16 n-segs

    const int oc_w = oc0 + wrow;
    const float* wptr = (oc_w < 128) ? (wq + oc_w * CIN)
                      : (oc_w < 256) ? (wk + (oc_w - 128) * CIN)
                                     : (wv + (oc_w - 256) * CIN);
    const float* xptr = x + (b * CIN + xc) * NPIX + n0 + xn;

    float acc[4][4] = {};

    for (int kc = 0; kc < CIN; kc += 16) {
        float4 w4 = *(const float4*)(wptr + kc + wseg * 4);
        float4 x4 = *(const float4*)(xptr + kc * NPIX);
        Ws[wrow][wseg*4+0] = w4.x; Ws[wrow][wseg*4+1] = w4.y;
        Ws[wrow][wseg*4+2] = w4.z; Ws[wrow][wseg*4+3] = w4.w;
        *(float4*)&Xs[xc][xn] = x4;
        __syncthreads();
        #pragma unroll
        for (int kk = 0; kk < 16; kk++) {
            const float a0 = Ws[ty*4+0][kk], a1 = Ws[ty*4+1][kk];
            const float a2 = Ws[ty*4+2][kk], a3 = Ws[ty*4+3][kk];
            const float4 bv = *(const float4*)&Xs[kk][tx*4];
            acc[0][0] = fmaf(a0, bv.x, acc[0][0]); acc[0][1] = fmaf(a0, bv.y, acc[0][1]);
            acc[0][2] = fmaf(a0, bv.z, acc[0][2]); acc[0][3] = fmaf(a0, bv.w, acc[0][3]);
            acc[1][0] = fmaf(a1, bv.x, acc[1][0]); acc[1][1] = fmaf(a1, bv.y, acc[1][1]);
            acc[1][2] = fmaf(a1, bv.z, acc[1][2]); acc[1][3] = fmaf(a1, bv.w, acc[1][3]);
            acc[2][0] = fmaf(a2, bv.x, acc[2][0]); acc[2][1] = fmaf(a2, bv.y, acc[2][1]);
            acc[2][2] = fmaf(a2, bv.z, acc[2][2]); acc[2][3] = fmaf(a2, bv.w, acc[2][3]);
            acc[3][0] = fmaf(a3, bv.x, acc[3][0]); acc[3][1] = fmaf(a3, bv.y, acc[3][1]);
            acc[3][2] = fmaf(a3, bv.z, acc[3][2]); acc[3][3] = fmaf(a3, bv.w, acc[3][3]);
        }
        __syncthreads();
    }

    // BN epilogue + scatter to Q/K/V layouts (channel-sub index is 4-aligned ->
    // transpose acc so the 4 "i" channels form one float4 store).
    const int rbase = oc0 + ty * 4;
    float sc[4], sh[4];
    if (oc0 < 128) {           // Q
        #pragma unroll
        for (int i = 0; i < 4; i++) {
            const int oc = rbase + i;
            const float r = rsqrtf(qv[oc] + EPSBN);
            sc[i] = qg[oc] * r; sh[i] = qb[oc] - qm[oc] * sc[i];
        }
        const int head = rbase >> 4, kdb = rbase & 15;
        float* base = g_Q + (b * HEADS + head) * NPIX * KD + kdb;
        #pragma unroll
        for (int j = 0; j < 4; j++) {
            const int n = n0 + tx * 4 + j;
            float4 v = make_float4(fmaf(acc[0][j], sc[0], sh[0]), fmaf(acc[1][j], sc[1], sh[1]),
                                   fmaf(acc[2][j], sc[2], sh[2]), fmaf(acc[3][j], sc[3], sh[3]));
            *(float4*)(base + n * KD) = v;
        }
    } else if (oc0 < 256) {    // K
        const int rb = rbase - 128;
        #pragma unroll
        for (int i = 0; i < 4; i++) {
            const int oc = rb + i;
            const float r = rsqrtf(kvv[oc] + EPSBN);
            sc[i] = kg[oc] * r; sh[i] = kb[oc] - km[oc] * sc[i];
        }
        const int head = rb >> 4, kdb = rb & 15;
        float* base = g_K + (b * HEADS + head) * NPIX * KD + kdb;
        #pragma unroll
        for (int j = 0; j < 4; j++) {
            const int n = n0 + tx * 4 + j;
            float4 v = make_float4(fmaf(acc[0][j], sc[0], sh[0]), fmaf(acc[1][j], sc[1], sh[1]),
                                   fmaf(acc[2][j], sc[2], sh[2]), fmaf(acc[3][j], sc[3], sh[3]));
            *(float4*)(base + n * KD) = v;
        }
    } else {                   // V
        const int rb = rbase - 256;
        #pragma unroll
        for (int i = 0; i < 4; i++) {
            const int oc = rb + i;
            const float r = rsqrtf(vvv[oc] + EPSBN);
            sc[i] = vg[oc] * r; sh[i] = vb[oc] - vm[oc] * sc[i];
        }
        const int head = rb >> 6, db = rb & 63;
        float* base = g_V + (b * HEADS + head) * NPIX * DV + db;
        #pragma unroll
        for (int j = 0; j < 4; j++) {
            const int n = n0 + tx * 4 + j;
            float4 v = make_float4(fmaf(acc[0][j], sc[0], sh[0]), fmaf(acc[1][j], sc[1], sh[1]),
                                   fmaf(acc[2][j], sc[2], sh[2]), fmaf(acc[3][j], sc[3], sh[3]));
            *(float4*)(base + n * DV) = v;
        }
    }
}

// ---------------------------------------------------------------------------
// Kernel 2: flash attention, fp32. grid (49, 16), block 256.
// Tile: 64 queries x 64 keys per iteration. Online softmax; P staged via smem.
// Thread (tx,ty) owns queries 4ty..4ty+3 and (keys|dims) 4tx..4tx+3.
// Row reductions via shfl_xor over the 16 tx lanes (stays inside half-warp).
// ---------------------------------------------------------------------------
__global__ __launch_bounds__(256, 3) void attn_kernel()
{
    __shared__ __align__(16) float Qt[16][64];   // transposed: [kd][q]
    __shared__ __align__(16) float Kt[16][64];   // transposed: [kd][k]
    __shared__ __align__(16) float Vs[64][64];   // [k][d]
    __shared__ float Ps[64][65];                 // [q][k], padded

    const int bh  = blockIdx.y;
    const int q0  = blockIdx.x * 64;
    const int tid = threadIdx.x, tx = tid & 15, ty = tid >> 4;
    const int lrow = tid >> 2, lseg = tid & 3;

    {   // load + transpose Q tile (once)
        float4 q4 = *(const float4*)(g_Q + (bh * NPIX + q0 + lrow) * KD + lseg * 4);
        Qt[lseg*4+0][lrow] = q4.x; Qt[lseg*4+1][lrow] = q4.y;
        Qt[lseg*4+2][lrow] = q4.z; Qt[lseg*4+3][lrow] = q4.w;
    }

    float m_i[4], l_i[4], o[4][4] = {};
    #pragma unroll
    for (int i = 0; i < 4; i++) { m_i[i] = -1e30f; l_i[i] = 0.f; }

    for (int kt = 0; kt < NT; kt++) {
        const int k0 = kt * 64;
        {   // load + transpose K tile
            float4 k4 = *(const float4*)(g_K + (bh * NPIX + k0 + lrow) * KD + lseg * 4);
            Kt[lseg*4+0][lrow] = k4.x; Kt[lseg*4+1][lrow] = k4.y;
            Kt[lseg*4+2][lrow] = k4.z; Kt[lseg*4+3][lrow] = k4.w;
        }
        {   // load V tile
            const float* vp = g_V + (bh * NPIX + k0) * DV;
            #pragma unroll
            for (int r = 0; r < 4; r++) {
                const int idx = tid + 256 * r;
                const int row = idx >> 4, seg = (idx & 15) * 4;
                *(float4*)&Vs[row][seg] = *(const float4*)(vp + row * DV + seg);
            }
        }
        __syncthreads();

        // S = Q K^T (4x4 per thread over 64x64 tile)
        float s[4][4] = {};
        #pragma unroll
        for (int kk = 0; kk < 16; kk++) {
            const float4 aq = *(const float4*)&Qt[kk][ty*4];
            const float4 bk = *(const float4*)&Kt[kk][tx*4];
            const float aa[4] = {aq.x, aq.y, aq.z, aq.w};
            const float bb[4] = {bk.x, bk.y, bk.z, bk.w};
            #pragma unroll
            for (int i = 0; i < 4; i++)
                #pragma unroll
                for (int j = 0; j < 4; j++)
                    s[i][j] = fmaf(aa[i], bb[j], s[i][j]);
        }

        // online softmax per query row
        #pragma unroll
        for (int i = 0; i < 4; i++) {
            float mt = fmaxf(fmaxf(s[i][0], s[i][1]), fmaxf(s[i][2], s[i][3]));
            #pragma unroll
            for (int off = 8; off >= 1; off >>= 1)
                mt = fmaxf(mt, __shfl_xor_sync(0xffffffffu, mt, off));
            const float mn   = fmaxf(m_i[i], mt);
            const float corr = __expf(m_i[i] - mn);
            m_i[i] = mn;
            float rs = 0.f;
            #pragma unroll
            for (int j = 0; j < 4; j++) { s[i][j] = __expf(s[i][j] - mn); rs += s[i][j]; }
            #pragma unroll
            for (int off = 8; off >= 1; off >>= 1)
                rs += __shfl_xor_sync(0xffffffffu, rs, off);
            l_i[i] = l_i[i] * corr + rs;
            #pragma unroll
            for (int j = 0; j < 4; j++) o[i][j] *= corr;
            Ps[ty*4+i][tx*4+0] = s[i][0]; Ps[ty*4+i][tx*4+1] = s[i][1];
            Ps[ty*4+i][tx*4+2] = s[i][2]; Ps[ty*4+i][tx*4+3] = s[i][3];
        }
        __syncthreads();

        // O += P @ V (thread owns dims 4tx..4tx+3 now)
        #pragma unroll 8
        for (int kk = 0; kk < 64; kk++) {
            const float4 vv = *(const float4*)&Vs[kk][tx*4];
            const float p0 = Ps[ty*4+0][kk], p1 = Ps[ty*4+1][kk];
            const float p2 = Ps[ty*4+2][kk], p3 = Ps[ty*4+3][kk];
            o[0][0] = fmaf(p0, vv.x, o[0][0]); o[0][1] = fmaf(p0, vv.y, o[0][1]);
            o[0][2] = fmaf(p0, vv.z, o[0][2]); o[0][3] = fmaf(p0, vv.w, o[0][3]);
            o[1][0] = fmaf(p1, vv.x, o[1][0]); o[1][1] = fmaf(p1, vv.y, o[1][1]);
            o[1][2] = fmaf(p1, vv.z, o[1][2]); o[1][3] = fmaf(p1, vv.w, o[1][3]);
            o[2][0] = fmaf(p2, vv.x, o[2][0]); o[2][1] = fmaf(p2, vv.y, o[2][1]);
            o[2][2] = fmaf(p2, vv.z, o[2][2]); o[2][3] = fmaf(p2, vv.w, o[2][3]);
            o[3][0] = fmaf(p3, vv.x, o[3][0]); o[3][1] = fmaf(p3, vv.y, o[3][1]);
            o[3][2] = fmaf(p3, vv.z, o[3][2]); o[3][3] = fmaf(p3, vv.w, o[3][3]);
        }
        __syncthreads();
    }

    #pragma unroll
    for (int i = 0; i < 4; i++) {
        const float inv = 1.f / l_i[i];
        float4 v = make_float4(o[i][0]*inv, o[i][1]*inv, o[i][2]*inv, o[i][3]*inv);
        *(float4*)(g_O + (bh * NPIX + q0 + ty*4 + i) * DV + tx*4) = v;
    }
}

// ---------------------------------------------------------------------------
// Kernel 3: out = BN(W_p @ relu(O)). grid (49, 6, 2), block 256.
// ---------------------------------------------------------------------------
__global__ __launch_bounds__(256, 3) void proj_kernel(
    const float* __restrict__ wp, const float* __restrict__ pg, const float* __restrict__ pb,
    const float* __restrict__ pm, const float* __restrict__ pvv, float* __restrict__ out)
{
    __shared__ float Ws[64][17];
    __shared__ __align__(16) float Xs[16][64];

    const int b   = blockIdx.z;
    const int oc0 = blockIdx.y * 64;
    const int n0  = blockIdx.x * 64;
    const int tid = threadIdx.x, tx = tid & 15, ty = tid >> 4;
    const int wrow = tid >> 2, wseg = tid & 3;
    const int xn   = tid >> 2, xseg = tid & 3;

    float acc[4][4] = {};

    for (int kc = 0; kc < DH; kc += 16) {
        float4 w4 = *(const float4*)(wp + (oc0 + wrow) * DH + kc + wseg * 4);
        const int head = kc >> 6, db = kc & 63;
        float4 x4 = *(const float4*)(g_O + ((b * HEADS + head) * NPIX + n0 + xn) * DV + db + xseg * 4);
        x4.x = fmaxf(x4.x, 0.f); x4.y = fmaxf(x4.y, 0.f);
        x4.z = fmaxf(x4.z, 0.f); x4.w = fmaxf(x4.w, 0.f);
        Ws[wrow][wseg*4+0] = w4.x; Ws[wrow][wseg*4+1] = w4.y;
        Ws[wrow][wseg*4+2] = w4.z; Ws[wrow][wseg*4+3] = w4.w;
        Xs[xseg*4+0][xn] = x4.x; Xs[xseg*4+1][xn] = x4.y;
        Xs[xseg*4+2][xn] = x4.z; Xs[xseg*4+3][xn] = x4.w;
        __syncthreads();
        #pragma unroll
        for (int kk = 0; kk < 16; kk++) {
            const float a0 = Ws[ty*4+0][kk], a1 = Ws[ty*4+1][kk];
            const float a2 = Ws[ty*4+2][kk], a3 = Ws[ty*4+3][kk];
            const float4 bv = *(const float4*)&Xs[kk][tx*4];
            acc[0][0] = fmaf(a0, bv.x, acc[0][0]); acc[0][1] = fmaf(a0, bv.y, acc[0][1]);
            acc[0][2] = fmaf(a0, bv.z, acc[0][2]); acc[0][3] = fmaf(a0, bv.w, acc[0][3]);
            acc[1][0] = fmaf(a1, bv.x, acc[1][0]); acc[1][1] = fmaf(a1, bv.y, acc[1][1]);
            acc[1][2] = fmaf(a1, bv.z, acc[1][2]); acc[1][3] = fmaf(a1, bv.w, acc[1][3]);
            acc[2][0] = fmaf(a2, bv.x, acc[2][0]); acc[2][1] = fmaf(a2, bv.y, acc[2][1]);
            acc[2][2] = fmaf(a2, bv.z, acc[2][2]); acc[2][3] = fmaf(a2, bv.w, acc[2][3]);
            acc[3][0] = fmaf(a3, bv.x, acc[3][0]); acc[3][1] = fmaf(a3, bv.y, acc[3][1]);
            acc[3][2] = fmaf(a3, bv.z, acc[3][2]); acc[3][3] = fmaf(a3, bv.w, acc[3][3]);
        }
        __syncthreads();
    }

    #pragma unroll
    for (int i = 0; i < 4; i++) {
        const int oc = oc0 + ty * 4 + i;
        const float r  = rsqrtf(pvv[oc] + EPSBN);
        const float sc = pg[oc] * r;
        const float sh = pb[oc] - pm[oc] * sc;
        float4 v = make_float4(fmaf(acc[i][0], sc, sh), fmaf(acc[i][1], sc, sh),
                               fmaf(acc[i][2], sc, sh), fmaf(acc[i][3], sc, sh));
        *(float4*)(out + (b * OCOUT + oc) * NPIX + n0 + tx * 4) = v;
    }
}

// ---------------------------------------------------------------------------
extern "C" void kernel_launch(void* const* d_in, const int* in_sizes, int n_in,
                              void* d_out, int out_size)
{
    (void)in_sizes; (void)n_in; (void)out_size;
    const float* x   = (const float*)d_in[0];
    const float* wq  = (const float*)d_in[1];
    const float* qg  = (const float*)d_in[2];
    const float* qb  = (const float*)d_in[3];
    const float* qm  = (const float*)d_in[4];
    const float* qv  = (const float*)d_in[5];
    const float* wk  = (const float*)d_in[6];
    const float* kg  = (const float*)d_in[7];
    const float* kb  = (const float*)d_in[8];
    const float* km  = (const float*)d_in[9];
    const float* kvv = (const float*)d_in[10];
    const float* wv  = (const float*)d_in[11];
    const float* vg  = (const float*)d_in[12];
    const float* vb  = (const float*)d_in[13];
    const float* vm  = (const float*)d_in[14];
    const float* vvv = (const float*)d_in[15];
    const float* wp  = (const float*)d_in[16];
    const float* pg  = (const float*)d_in[17];
    const float* pb  = (const float*)d_in[18];
    const float* pm  = (const float*)d_in[19];
    const float* pvv = (const float*)d_in[20];
    float* out = (float*)d_out;

    dim3 blk(256);
    qkv_kernel<<<dim3(NT, 12, BATCH), blk>>>(x, wq, wk, wv,
                                             qg, qb, qm, qv,
                                             kg, kb, km, kvv,
                                             vg, vb, vm, vvv);
    attn_kernel<<<dim3(NT, BH), blk>>>();
    proj_kernel<<<dim3(NT, 6, BATCH), blk>>>(wp, pg, pb, pm, pvv, out);
}